// round 16
// baseline (speedup 1.0000x reference)
#include <cuda_runtime.h>
#include <cuda_bf16.h>
#include <stdint.h>

// Problem constants
#define Bc   16
#define Sc   1024
#define Ec   8192
#define Dc   512
#define Hc   8
#define DKc  64
#define Lc   2
#define Nc   (Bc*Sc)     // 16384 nodes
#define BEc  (Bc*Ec)     // 131072 edge slots
#define HDc  (Hc*DKc)    // 512

#if defined(__CUDA_ARCH_FEAT_SM103_ALL) || defined(__CUDA_ARCH_FEAT_SM100_ALL)
#define HAS_TC 1
#else
#define HAS_TC 0
#endif

// ---------------- device scratch (static, no allocation) ----------------
__device__ int   g_starts[Bc+1];
__device__ int   g_src[BEc], g_tgt[BEc], g_dr[BEc], g_da[BEc], g_rp[BEc];
__device__ int   g_deg[Nc], g_rowptr[Nc+1], g_cnt[Nc], g_csr[BEc];
__device__ __align__(16) float g_h[Nc*Dc];
__device__ __align__(16) float g_q[Nc*HDc], g_k[Nc*HDc], g_v[Nc*HDc];
__device__ __align__(16) float g_rel[BEc*DKc];
__device__ float g_logit[BEc*Hc];
__device__ float g_m[Nc*Hc], g_den[Nc*Hc];
__device__ __align__(16) float g_agg[Nc*HDc];
__device__ __align__(16) float g_tmp[Nc*Dc];
__device__ __align__(16) __nv_bfloat16 g_ah[Nc*Dc], g_al[Nc*Dc];
__device__ __align__(16) __nv_bfloat16 g_wh[8*Dc*Dc], g_wl[8*Dc*Dc];   // transposed [mat][n][k]

// ---------------- PTX helpers ----------------
__device__ __forceinline__ uint32_t smem_u32(const void* p) {
    uint32_t a;
    asm("{ .reg .u64 t; cvta.to.shared.u64 t, %1; cvt.u32.u64 %0, t; }" : "=r"(a) : "l"(p));
    return a;
}

#if HAS_TC
__device__ __forceinline__ uint32_t elect_one() {
    uint32_t p;
    asm volatile("{\n\t.reg .pred p;\n\telect.sync _|p, 0xFFFFFFFF;\n\tselp.b32 %0, 1, 0, p;\n\t}" : "=r"(p));
    return p;
}
#define TC_ALLOC(sm, n)   asm volatile("tcgen05.alloc.cta_group::1.sync.aligned.shared::cta.b32 [%0], %1;" :: "r"(sm), "r"(n) : "memory")
#define TC_DEALLOC(t, n)  asm volatile("tcgen05.dealloc.cta_group::1.sync.aligned.b32 %0, %1;" :: "r"(t), "r"(n))
#define TC_RELINQ()       asm volatile("tcgen05.relinquish_alloc_permit.cta_group::1.sync.aligned;")
#define TC_COMMIT(mb)     asm volatile("tcgen05.commit.cta_group::1.mbarrier::arrive::one.shared::cluster.b64 [%0];" :: "r"(mb) : "memory")
#define TC_FENCE_AFTER()  asm volatile("tcgen05.fence::after_thread_sync;" ::: "memory")
#define TC_FENCE_BEFORE() asm volatile("tcgen05.fence::before_thread_sync;" ::: "memory")
#define TC_WAIT_LD()      asm volatile("tcgen05.wait::ld.sync.aligned;" ::: "memory")
#define FENCE_ASYNC()     asm volatile("fence.proxy.async.shared::cta;" ::: "memory")
#define MBAR_INIT(mb, c)  asm volatile("mbarrier.init.shared.b64 [%0], %1;" :: "r"(mb), "r"(c) : "memory")
#define MBAR_INVAL(mb)    asm volatile("mbarrier.inval.shared.b64 [%0];" :: "r"(mb) : "memory")
#define CP16(sa, gp)      asm volatile("cp.async.cg.shared.global [%0], [%1], 16;" :: "r"(sa), "l"(gp))
#define CP_COMMIT()       asm volatile("cp.async.commit_group;" ::: "memory")
#define CP_WAIT1()        asm volatile("cp.async.wait_group 1;" ::: "memory")
#define CP_WAIT0()        asm volatile("cp.async.wait_group 0;" ::: "memory")

#define MBAR_WAIT(mb, ph) do {                                              \
    uint32_t _m = (mb), _p = (ph), _d;                                      \
    asm volatile("{\n\t.reg .pred p;\n\t"                                   \
        "mbarrier.try_wait.parity.acquire.cta.shared::cta.b64 p, [%1], %2;\n\t" \
        "selp.b32 %0, 1, 0, p;\n\t}" : "=r"(_d) : "r"(_m), "r"(_p) : "memory"); \
    if (!_d) {                                                              \
        asm volatile("{\n\t.reg .pred P1;\n\t"                              \
            "WL_%=:\n\t"                                                    \
            "mbarrier.try_wait.parity.acquire.cta.shared::cta.b64 P1, [%0], %1, 0x989680;\n\t" \
            "@P1 bra.uni WD_%=;\n\t"                                        \
            "bra.uni WL_%=;\n\t"                                            \
            "WD_%=:\n\t}" :: "r"(_m), "r"(_p) : "memory");                  \
    }                                                                       \
} while (0)

__device__ __forceinline__ void mma_bf16_ss(uint32_t d, uint64_t da, uint64_t db,
                                            uint32_t idesc, uint32_t en) {
    asm volatile(
        "{\n\t.reg .pred p;\n\tsetp.ne.u32 p, %5, 0;\n\t"
        "tcgen05.mma.cta_group::1.kind::f16 [%0], %1, %2, %3, {%4,%4,%4,%4}, p;\n\t}"
        :: "r"(d), "l"(da), "l"(db), "r"(idesc), "r"(0u), "r"(en) : "memory");
}

__device__ __forceinline__ void ldtm_x32(uint32_t* r, uint32_t ta) {
    asm volatile(
        "tcgen05.ld.sync.aligned.32x32b.x32.b32 "
        "{%0,%1,%2,%3,%4,%5,%6,%7,%8,%9,%10,%11,%12,%13,%14,%15,"
        "%16,%17,%18,%19,%20,%21,%22,%23,%24,%25,%26,%27,%28,%29,%30,%31}, [%32];"
        : "=r"(r[0]),"=r"(r[1]),"=r"(r[2]),"=r"(r[3]),"=r"(r[4]),"=r"(r[5]),"=r"(r[6]),"=r"(r[7]),
          "=r"(r[8]),"=r"(r[9]),"=r"(r[10]),"=r"(r[11]),"=r"(r[12]),"=r"(r[13]),"=r"(r[14]),"=r"(r[15]),
          "=r"(r[16]),"=r"(r[17]),"=r"(r[18]),"=r"(r[19]),"=r"(r[20]),"=r"(r[21]),"=r"(r[22]),"=r"(r[23]),
          "=r"(r[24]),"=r"(r[25]),"=r"(r[26]),"=r"(r[27]),"=r"(r[28]),"=r"(r[29]),"=r"(r[30]),"=r"(r[31])
        : "r"(ta));
}

// SW64 descriptor base: layout=4, version=1, SBO=32, LBO=1 (64B rows, atom = 8r x 64B)
#define DESC_SW64 ((4ull<<61) | (1ull<<46) | (32ull<<32) | (1ull<<16))
#define MK_DESC64(a) (DESC_SW64 | ((uint64_t)((a) >> 4) & 0x3FFFull))
// idesc: f32 accum, A=BF16, B=BF16, M=128, N=256
#define GEMM_IDESC 0x08400490u
#endif  // HAS_TC

// ---------------- small utility kernels ----------------
__global__ void k_zero_f(float* p, int n) {
    int i = blockIdx.x * blockDim.x + threadIdx.x;
    if (i < n) p[i] = 0.f;
}

__global__ void k_zero_counts() {
    int i = blockIdx.x * blockDim.x + threadIdx.x;
    if (i < Nc) { g_deg[i] = 0; g_cnt[i] = 0; }
}

__global__ void k_starts(const int* __restrict__ edge_len) {
    int s = 0;
    for (int b = 0; b < Bc; b++) { g_starts[b] = s; s += edge_len[b]; }
    g_starts[Bc] = s;
}

// flatten + degree histogram in one pass
__global__ void k_flatten(const int* __restrict__ edge_index,
                          const int* __restrict__ relpos_idx,
                          const int* __restrict__ deprel_idx,
                          const int* __restrict__ deparc_idx,
                          const int* __restrict__ edge_len) {
    int i = blockIdx.x * blockDim.x + threadIdx.x;
    if (i >= BEc) return;
    int b = i >> 13;
    int e = i & (Ec - 1);
    if (e < edge_len[b]) {
        int p = g_starts[b] + e;
        int tg = edge_index[(size_t)i * 2 + 1] + b * Sc;
        g_src[p] = edge_index[(size_t)i * 2 + 0] + b * Sc;
        g_tgt[p] = tg;
        g_dr[p]  = deprel_idx[i];
        g_da[p]  = deparc_idx[i];
        g_rp[p]  = relpos_idx[i];
        atomicAdd(&g_deg[tg], 1);
    }
}

__global__ void k_scan() {
    __shared__ int sh[1024];
    int t = threadIdx.x;
    int base = t * 16;
    int loc[16];
    int tot = 0;
    #pragma unroll
    for (int j = 0; j < 16; j++) { loc[j] = tot; tot += g_deg[base + j]; }
    sh[t] = tot;
    __syncthreads();
    for (int off = 1; off < 1024; off <<= 1) {
        int v = (t >= off) ? sh[t - off] : 0;
        __syncthreads();
        sh[t] += v;
        __syncthreads();
    }
    int excl = sh[t] - tot;
    #pragma unroll
    for (int j = 0; j < 16; j++) g_rowptr[base + j] = excl + loc[j];
    if (t == 1023) g_rowptr[Nc] = sh[1023];
}

__global__ void k_scatter() {
    int i = blockIdx.x * blockDim.x + threadIdx.x;
    if (i >= g_starts[Bc]) return;
    int tg = g_tgt[i];
    int slot = g_rowptr[tg] + atomicAdd(&g_cnt[tg], 1);
    g_csr[slot] = i;
}

// ---------------- weight prep: transpose + bf16 split (tc path only) ----------------
__global__ void k_wprep(const float* __restrict__ Wq, const float* __restrict__ Wk,
                        const float* __restrict__ Wv, const float* __restrict__ Wo) {
#if HAS_TC
    int mat = blockIdx.y;
    int l = mat >> 2, m = mat & 3;
    const float* W = (m == 0 ? Wq : m == 1 ? Wk : m == 2 ? Wv : Wo) + (size_t)l * Dc * Dc;
    int i = blockIdx.x * 256 + threadIdx.x;
    int n = i & 511, k = i >> 9;
    float v = W[(size_t)k * 512 + n];
    __nv_bfloat16 hi = __float2bfloat16(v);
    float lo = v - __bfloat162float(hi);
    size_t o = (size_t)mat * 262144 + (size_t)n * 512 + k;
    g_wh[o] = hi;
    g_wl[o] = __float2bfloat16(lo);
#endif
}

// ---------------- activation split (input only) ----------------
__global__ void k_split(const float* __restrict__ ext) {
#if HAS_TC
    int i = blockIdx.x * 256 + threadIdx.x;
    float v = ext[i];
    __nv_bfloat16 hi = __float2bfloat16(v);
    g_ah[i] = hi;
    g_al[i] = __float2bfloat16(v - __bfloat162float(hi));
#endif
}

// ---------------- tcgen05 GEMM (sm_103a only) ----------------
// mode 0: fused QKV grid (6,128): x -> {q,k,v} x {N-half}; mode 1: O-proj grid (2,128).
// 128M x 256N per CTA, K=32 chunks (SW64), double-buffered 48KB, cp.async prefetch,
// N=256 MMA dispatches. ~99KB SMEM -> 2 CTAs/SM.
#define BUF_BYTES 49152
__global__ __launch_bounds__(256) void gemm_tc(int l, int mode) {
#if HAS_TC
    __shared__ uint32_t s_tmem[1];
    __shared__ __align__(8) unsigned long long s_mbar[2];
    extern __shared__ __align__(16) char dsm[];

    const int tid = threadIdx.x;
    const int wid = tid >> 5, lane = tid & 31;

    int mi, half;
    if (mode == 0) { mi = blockIdx.x >> 1; half = blockIdx.x & 1; }
    else           { mi = 3;               half = blockIdx.x; }
    const int mat = l * 4 + mi;
    float* C = (mi == 0) ? g_q : (mi == 1 ? g_k : (mi == 2 ? g_v : g_tmp));
    const int bm0 = blockIdx.y * 128;
    const int bn0 = half * 256;

    uint32_t dyn0 = smem_u32(dsm);
    uint32_t base = (dyn0 + 1023) & ~1023u;
    char* pb = dsm + (base - dyn0);
    const uint32_t mb[2] = { smem_u32(&s_mbar[0]), smem_u32(&s_mbar[1]) };

    const __nv_bfloat16* __restrict__ Wh = g_wh + (size_t)mat * 262144;
    const __nv_bfloat16* __restrict__ Wl = g_wl + (size_t)mat * 262144;

    if (wid == 0) {
        TC_ALLOC(smem_u32(s_tmem), 256);
        TC_RELINQ();
    }
    if (tid == 0) { MBAR_INIT(mb[0], 1); MBAR_INIT(mb[1], 1); }
    __syncthreads();
    uint32_t tmem;
    asm volatile("ld.shared.b32 %0, [%1];" : "=r"(tmem) : "r"(smem_u32(s_tmem)));

    auto load_chunk = [&](int j) {
        const uint32_t bufo = base + (uint32_t)(j & 1) * BUF_BYTES;
        const int k0 = j * 32;
        #pragma unroll
        for (int it = 0; it < 2; it++) {
            int u = tid + it * 256;
            int row = u >> 2, c16 = u & 3;
            uint32_t off = (uint32_t)row * 64 + (uint32_t)c16 * 16;
            uint32_t sw = off ^ ((off >> 3) & 0x30);
            const char* gh = (const char*)(g_ah + (size_t)(bm0 + row) * 512 + k0) + c16 * 16;
            const char* gl = (const char*)(g_al + (size_t)(bm0 + row) * 512 + k0) + c16 * 16;
            CP16(bufo + sw, gh);
            CP16(bufo + 8192 + sw, gl);
        }
        #pragma unroll
        for (int it = 0; it < 4; it++) {
            int u = tid + it * 256;
            int row = u >> 2, c16 = u & 3;
            uint32_t off = (uint32_t)row * 64 + (uint32_t)c16 * 16;
            uint32_t sw = off ^ ((off >> 3) & 0x30);
            const char* gh = (const char*)(Wh + (size_t)(bn0 + row) * 512 + k0) + c16 * 16;
            const char* gl = (const char*)(Wl + (size_t)(bn0 + row) * 512 + k0) + c16 * 16;
            CP16(bufo + 16384 + sw, gh);
            CP16(bufo + 32768 + sw, gl);
        }
        CP_COMMIT();
    };

    load_chunk(0);
    for (int c = 0; c < 16; c++) {
        const int j = c + 1;
        if (j < 16) {
            if (j >= 2) MBAR_WAIT(mb[j & 1], ((j - 2) >> 1) & 1);
            load_chunk(j);
            CP_WAIT1();
        } else {
            CP_WAIT0();
        }
        __syncthreads();

        if (wid == 0) {
            if (elect_one()) {
                FENCE_ASYNC();
                const uint32_t bufo = base + (uint32_t)(c & 1) * BUF_BYTES;
                const uint64_t dAh = MK_DESC64(bufo);
                const uint64_t dAl = MK_DESC64(bufo + 8192);
                const uint64_t dBh = MK_DESC64(bufo + 16384);
                const uint64_t dBl = MK_DESC64(bufo + 32768);
                #pragma unroll
                for (int ks = 0; ks < 2; ks++) {
                    const uint64_t ofs = (uint64_t)(ks * 2);
                    mma_bf16_ss(tmem, dAh + ofs, dBh + ofs, GEMM_IDESC,
                                (c == 0 && ks == 0) ? 0u : 1u);
                    mma_bf16_ss(tmem, dAh + ofs, dBl + ofs, GEMM_IDESC, 1u);
                    mma_bf16_ss(tmem, dAl + ofs, dBh + ofs, GEMM_IDESC, 1u);
                }
                TC_COMMIT(mb[c & 1]);
            }
        }
    }
    MBAR_WAIT(mb[0], 1);
    MBAR_WAIT(mb[1], 1);
    TC_FENCE_AFTER();

    // epilogue: two 128-col passes; TMEM -> padded SMEM stage (stride 129) -> global
    float* stage = (float*)pb;
    const int rrow = (wid & 3) * 32 + lane;
    const int q0 = (wid >> 2) * 64;
    #pragma unroll
    for (int p = 0; p < 2; p++) {
        #pragma unroll
        for (int cb = 0; cb < 2; cb++) {
            uint32_t regs[32];
            ldtm_x32(regs, tmem + p * 128 + q0 + cb * 32);
            TC_WAIT_LD();
            #pragma unroll
            for (int j = 0; j < 32; j++)
                stage[rrow * 129 + q0 + cb * 32 + j] = __uint_as_float(regs[j]);
        }
        TC_FENCE_BEFORE();
        __syncthreads();
        {
            int col = tid & 127;
            int rb = tid >> 7;
            for (int r = rb; r < 128; r += 2)
                C[(size_t)(bm0 + r) * 512 + bn0 + p * 128 + col] = stage[r * 129 + col];
        }
        __syncthreads();
    }
    if (tid == 0) { MBAR_INVAL(mb[0]); MBAR_INVAL(mb[1]); }
    if (wid == 0) TC_DEALLOC(tmem, 256);
#endif  // HAS_TC
}

// ---------------- SIMT fallback SGEMM (empty when tcgen05 path is compiled) -------
#define GM 16384
#define GN 512
#define GK 512
__global__ __launch_bounds__(256) void gemm_simt(const float* __restrict__ Aext,
                                                 const float* __restrict__ Bw,
                                                 int asel, int csel) {
#if !HAS_TC
    const float* A = (asel == 0) ? Aext : (asel == 1 ? g_h : g_agg);
    float* C = (csel == 0) ? g_q : (csel == 1 ? g_k : (csel == 2 ? g_v : g_tmp));

    __shared__ float As[8][128];
    __shared__ float Bs[8][128];

    int bm0 = blockIdx.y * 128;
    int bn0 = blockIdx.x * 128;
    int t = threadIdx.x;
    int ty = t >> 4, tx = t & 15;

    int arow = t >> 1;
    int acol = (t & 1) * 4;
    int brow = t >> 5;
    int bcol = (t & 31) * 4;

    float acc[8][8];
    #pragma unroll
    for (int i = 0; i < 8; i++)
        #pragma unroll
        for (int j = 0; j < 8; j++) acc[i][j] = 0.f;

    for (int k0 = 0; k0 < GK; k0 += 8) {
        float4 av = *(const float4*)(A + (size_t)(bm0 + arow) * GK + k0 + acol);
        As[acol + 0][arow] = av.x;
        As[acol + 1][arow] = av.y;
        As[acol + 2][arow] = av.z;
        As[acol + 3][arow] = av.w;
        float4 bv = *(const float4*)(Bw + (size_t)(k0 + brow) * GN + bn0 + bcol);
        *(float4*)&Bs[brow][bcol] = bv;
        __syncthreads();
        #pragma unroll
        for (int kk = 0; kk < 8; kk++) {
            float4 a0 = *(float4*)&As[kk][ty * 8];
            float4 a1 = *(float4*)&As[kk][ty * 8 + 4];
            float4 b0 = *(float4*)&Bs[kk][tx * 8];
            float4 b1 = *(float4*)&Bs[kk][tx * 8 + 4];
            float a[8] = {a0.x, a0.y, a0.z, a0.w, a1.x, a1.y, a1.z, a1.w};
            float b[8] = {b0.x, b0.y, b0.z, b0.w, b1.x, b1.y, b1.z, b1.w};
            #pragma unroll
            for (int i = 0; i < 8; i++)
                #pragma unroll
                for (int j = 0; j < 8; j++)
                    acc[i][j] += a[i] * b[j];
        }
        __syncthreads();
    }
    #pragma unroll
    for (int i = 0; i < 8; i++) {
        float* crow = C + (size_t)(bm0 + ty * 8 + i) * GN + bn0 + tx * 8;
        float4 c0 = {acc[i][0], acc[i][1], acc[i][2], acc[i][3]};
        float4 c1 = {acc[i][4], acc[i][5], acc[i][6], acc[i][7]};
        *(float4*)(crow) = c0;
        *(float4*)(crow + 4) = c1;
    }
#endif  // !HAS_TC
}

// ---------------- logits in CSR order: block per node, q hoisted ----------------
// Warp-per-edge over the node's incoming edges; computes rel (tables), writes
// g_rel + g_logit, accumulates per-head online (m,d); warps merge via SMEM;
// final (m, den) written to g_m/g_den.
__global__ __launch_bounds__(128) void k_logit(const float* __restrict__ dre,
                                               const float* __restrict__ dae,
                                               const float* __restrict__ rpe) {
    const int n = blockIdx.x;
    const int t = threadIdx.x;
    const int wid = t >> 5, lane = t & 31;
    const int beg = g_rowptr[n], end = g_rowptr[n + 1];
    const int l16 = lane & 15, grp = lane >> 4;

    __shared__ float sm_m[4][8], sm_d[4][8];

    // q fragments loaded once per node: lane's 4 heads (h = h2*2 + grp)
    const float4* qb = (const float4*)(g_q + (size_t)n * HDc);
    float4 q4[4];
    #pragma unroll
    for (int h2 = 0; h2 < 4; h2++) q4[h2] = qb[(h2 * 2 + grp) * 16 + l16];

    float rm[4], rd[4];
    #pragma unroll
    for (int h2 = 0; h2 < 4; h2++) { rm[h2] = -1e30f; rd[h2] = 0.f; }

    for (int e = beg + wid; e < end; e += 4) {
        int i = g_csr[e];
        int src = g_src[i];
        float4 a = ((const float4*)(dre + (size_t)g_dr[i] * DKc))[l16];
        float4 b = ((const float4*)(dae + (size_t)g_da[i] * DKc))[l16];
        float4 cc = ((const float4*)(rpe + (size_t)g_rp[i] * DKc))[l16];
        float4 r4 = make_float4(a.x + b.x + cc.x, a.y + b.y + cc.y,
                                a.z + b.z + cc.z, a.w + b.w + cc.w);
        if (grp == 0) ((float4*)(g_rel + (size_t)i * DKc))[l16] = r4;
        const float4* kb = (const float4*)(g_k + (size_t)src * HDc);
        #pragma unroll
        for (int h2 = 0; h2 < 4; h2++) {
            int h = h2 * 2 + grp;
            float4 k4 = kb[h * 16 + l16];
            float acc = q4[h2].x * (k4.x + r4.x) + q4[h2].y * (k4.y + r4.y)
                      + q4[h2].z * (k4.z + r4.z) + q4[h2].w * (k4.w + r4.w);
            acc += __shfl_xor_sync(0xffffffffu, acc, 8);
            acc += __shfl_xor_sync(0xffffffffu, acc, 4);
            acc += __shfl_xor_sync(0xffffffffu, acc, 2);
            acc += __shfl_xor_sync(0xffffffffu, acc, 1);
            float logit = acc * 0.125f;
            if (l16 == 0) g_logit[(size_t)i * Hc + h] = logit;
            float nm = fmaxf(rm[h2], logit);
            rd[h2] = rd[h2] * __expf(rm[h2] - nm) + __expf(logit - nm);
            rm[h2] = nm;
        }
    }
    if (l16 == 0) {
        #pragma unroll
        for (int h2 = 0; h2 < 4; h2++) {
            sm_m[wid][h2 * 2 + grp] = rm[h2];
            sm_d[wid][h2 * 2 + grp] = rd[h2];
        }
    }
    __syncthreads();
    if (t < 8) {
        float m = -1e30f;
        #pragma unroll
        for (int w = 0; w < 4; w++) m = fmaxf(m, sm_m[w][t]);
        float d = 0.f;
        #pragma unroll
        for (int w = 0; w < 4; w++) d += sm_d[w][t] * __expf(sm_m[w][t] - m);
        g_m[n * Hc + t] = m;
        g_den[n * Hc + t] = d + 1e-9f;
    }
}

// ---------------- aggregate (phase-2 only; reads g_m/g_den/g_rel) ----------------
__global__ __launch_bounds__(128) void k_agg(float* __restrict__ attn_out) {
    const int n = blockIdx.x;
    const int t = threadIdx.x;
    const int beg = g_rowptr[n], end = g_rowptr[n + 1];
    const int dim0 = t * 4;
    const int h = dim0 >> 6;
    const int d0 = dim0 & 63;
    const float mh = g_m[n * Hc + h];
    const float dh = g_den[n * Hc + h];
    float acc0 = 0.f, acc1 = 0.f, acc2 = 0.f, acc3 = 0.f;
    for (int e = beg; e < end; e++) {
        int i = g_csr[e];
        float alpha = __expf(g_logit[(size_t)i * Hc + h] - mh) / dh;
        int src = g_src[i];
        const float* vp = g_v + (size_t)src * HDc + dim0;
        const float* rp = g_rel + (size_t)i * DKc + d0;
        acc0 += alpha * (vp[0] + rp[0]);
        acc1 += alpha * (vp[1] + rp[1]);
        acc2 += alpha * (vp[2] + rp[2]);
        acc3 += alpha * (vp[3] + rp[3]);
        if ((t & 15) == 0) attn_out[(size_t)i * Hc + h] = alpha;
    }
    size_t o = (size_t)n * HDc + dim0;
    float* ap = g_agg + o;
    ap[0] = acc0; ap[1] = acc1; ap[2] = acc2; ap[3] = acc3;
#if HAS_TC
    float vv[4] = {acc0, acc1, acc2, acc3};
    #pragma unroll
    for (int j = 0; j < 4; j++) {
        __nv_bfloat16 hi = __float2bfloat16(vv[j]);
        g_ah[o + j] = hi;
        g_al[o + j] = __float2bfloat16(vv[j] - __bfloat162float(hi));
    }
#endif
}

// ---------------- residual + LayerNorm (+ReLU); emits next-layer bf16 split -------
__global__ void k_ln(const float* __restrict__ hin_ext, int use_ext,
                     const float* __restrict__ lnsc,
                     const float* __restrict__ lnbi,
                     float* __restrict__ reps_out, int do_relu) {
    int n = blockIdx.x;
    int t = threadIdx.x;
    int lane = t & 31, warp = t >> 5;
    const float* hin = use_ext ? hin_ext : g_h;
    const float* row = g_tmp + (size_t)n * Dc;
    const float* hrow = hin + (size_t)n * Dc;
    float x[4];
    float s = 0.f;
    #pragma unroll
    for (int j = 0; j < 4; j++) {
        x[j] = row[t * 4 + j] + hrow[t * 4 + j];
        s += x[j];
    }
    __shared__ float red[4];
    #pragma unroll
    for (int off = 16; off; off >>= 1) s += __shfl_xor_sync(0xffffffffu, s, off);
    if (lane == 0) red[warp] = s;
    __syncthreads();
    float mean = (red[0] + red[1] + red[2] + red[3]) * (1.f / Dc);
    __syncthreads();
    float vs = 0.f;
    #pragma unroll
    for (int j = 0; j < 4; j++) { float d = x[j] - mean; vs += d * d; }
    #pragma unroll
    for (int off = 16; off; off >>= 1) vs += __shfl_xor_sync(0xffffffffu, vs, off);
    if (lane == 0) red[warp] = vs;
    __syncthreads();
    float var = (red[0] + red[1] + red[2] + red[3]) * (1.f / Dc);
    float inv = rsqrtf(var + 1e-5f);
    #pragma unroll
    for (int j = 0; j < 4; j++) {
        int dim = t * 4 + j;
        float y = (x[j] - mean) * inv * lnsc[dim] + lnbi[dim];
        if (do_relu) y = fmaxf(y, 0.f);
        size_t o = (size_t)n * Dc + dim;
        reps_out[o] = y;
        g_h[o] = y;
#if HAS_TC
        __nv_bfloat16 hi = __float2bfloat16(y);
        g_ah[o] = hi;
        g_al[o] = __float2bfloat16(y - __bfloat162float(hi));
#endif
    }
}

// ---------------- launch ----------------
extern "C" void kernel_launch(void* const* d_in, const int* in_sizes, int n_in,
                              void* d_out, int out_size) {
    const float* inp        = (const float*)d_in[0];
    const int*   edge_len   = (const int*)d_in[2];
    const int*   edge_index = (const int*)d_in[3];
    const int*   relpos_idx = (const int*)d_in[4];
    const int*   deprel_idx = (const int*)d_in[6];
    const int*   deparc_idx = (const int*)d_in[7];
    const float* Wq  = (const float*)d_in[14];
    const float* Wk  = (const float*)d_in[15];
    const float* Wv  = (const float*)d_in[16];
    const float* Wo  = (const float*)d_in[17];
    const float* dre = (const float*)d_in[18];
    const float* dae = (const float*)d_in[19];
    const float* rpe = (const float*)d_in[20];
    const float* lnsc = (const float*)d_in[21];
    const float* lnbi = (const float*)d_in[22];

    float* out  = (float*)d_out;
    float* reps = out;                          // (L, N, D)
    float* attn = out + (size_t)Lc * Nc * Dc;   // (L, BE, H)

    const int GEMM_SMEM = 2 * BUF_BYTES + 1024;   // 99328 -> 2 CTAs/SM
    cudaFuncSetAttribute(gemm_tc, cudaFuncAttributeMaxDynamicSharedMemorySize, GEMM_SMEM);

    // detect which GEMM path this cubin compiled (deterministic per binary):
    // tc body uses ~64 regs; empty body compiles to a handful.
    cudaFuncAttributes fa_tc{};
    cudaFuncGetAttributes(&fa_tc, gemm_tc);
    const bool use_tc = fa_tc.numRegs > 32;

    dim3 ggrid_qkv(6, 128);
    dim3 ggrid_o(2, 128);
    dim3 ggrid_simt(4, 128);

    // prep needed by first GEMM (keeps first gemm_tc at my 4th launch for ncu)
    k_wprep<<<dim3(1024, 8), 256>>>(Wq, Wk, Wv, Wo);
    k_split<<<(Nc * Dc) / 256, 256>>>(inp);
    k_zero_f<<<(Lc * BEc * Hc + 255) / 256, 256>>>(attn, Lc * BEc * Hc);

    // layer-0 QKV (fused)
    if (use_tc) {
        gemm_tc<<<ggrid_qkv, 256, GEMM_SMEM>>>(0, 0);
    } else {
        gemm_simt<<<ggrid_simt, 256>>>(inp, Wq, 0, 0);
        gemm_simt<<<ggrid_simt, 256>>>(inp, Wk, 0, 1);
        gemm_simt<<<ggrid_simt, 256>>>(inp, Wv, 0, 2);
    }

    // edge preprocessing (independent of GEMMs)
    k_zero_counts<<<(Nc + 255) / 256, 256>>>();
    k_starts<<<1, 1>>>(edge_len);
    k_flatten<<<BEc / 256, 256>>>(edge_index, relpos_idx, deprel_idx, deparc_idx, edge_len);
    k_scan<<<1, 1024>>>();
    k_scatter<<<BEc / 256, 256>>>();

    for (int l = 0; l < Lc; l++) {
        if (l > 0) {
            const size_t woff = (size_t)l * Dc * HDc;
            if (use_tc) {
                gemm_tc<<<ggrid_qkv, 256, GEMM_SMEM>>>(l, 0);
            } else {
                gemm_simt<<<ggrid_simt, 256>>>(inp, Wq + woff, 1, 0);
                gemm_simt<<<ggrid_simt, 256>>>(inp, Wk + woff, 1, 1);
                gemm_simt<<<ggrid_simt, 256>>>(inp, Wv + woff, 1, 2);
            }
        }

        k_logit<<<Nc, 128>>>(dre + (size_t)l * 50 * DKc,
                             dae + (size_t)l * 3 * DKc,
                             rpe + (size_t)l * 21 * DKc);
        k_agg<<<Nc, 128>>>(attn + (size_t)l * BEc * Hc);

        if (use_tc) {
            gemm_tc<<<ggrid_o, 256, GEMM_SMEM>>>(l, 1);    // agg @ Wo -> g_tmp
        } else {
            gemm_simt<<<ggrid_simt, 256>>>(inp, Wo + (size_t)l * HDc * Dc, 2, 3);
        }

        k_ln<<<Nc, 128>>>(inp, (l == 0) ? 1 : 0,
                          lnsc + (size_t)l * Dc, lnbi + (size_t)l * Dc,
                          reps + (size_t)l * Nc * Dc, (l < Lc - 1) ? 1 : 0);
    }
}

// round 17
// speedup vs baseline: 1.0884x; 1.0884x over previous
#include <cuda_runtime.h>
#include <cuda_bf16.h>
#include <stdint.h>

// Problem constants
#define Bc   16
#define Sc   1024
#define Ec   8192
#define Dc   512
#define Hc   8
#define DKc  64
#define Lc   2
#define Nc   (Bc*Sc)     // 16384 nodes
#define BEc  (Bc*Ec)     // 131072 edge slots
#define HDc  (Hc*DKc)    // 512

#if defined(__CUDA_ARCH_FEAT_SM103_ALL) || defined(__CUDA_ARCH_FEAT_SM100_ALL)
#define HAS_TC 1
#else
#define HAS_TC 0
#endif

// ---------------- device scratch (static, no allocation) ----------------
__device__ int   g_starts[Bc+1];
__device__ int   g_src[BEc], g_tgt[BEc], g_dr[BEc], g_da[BEc], g_rp[BEc];
__device__ int   g_deg[Nc], g_rowptr[Nc+1], g_cnt[Nc], g_csr[BEc];
__device__ __align__(16) float g_h[Nc*Dc];
__device__ __align__(16) float g_q[Nc*HDc], g_k[Nc*HDc], g_v[Nc*HDc];
__device__ __align__(16) float g_rel[BEc*DKc];
__device__ float g_logit[BEc*Hc];
__device__ __align__(16) float g_agg[Nc*HDc];
__device__ __align__(16) float g_tmp[Nc*Dc];
__device__ __align__(16) __nv_bfloat16 g_ah[Nc*Dc], g_al[Nc*Dc];
__device__ __align__(16) __nv_bfloat16 g_wh[8*Dc*Dc], g_wl[8*Dc*Dc];   // transposed [mat][n][k]

// ---------------- PTX helpers ----------------
__device__ __forceinline__ uint32_t smem_u32(const void* p) {
    uint32_t a;
    asm("{ .reg .u64 t; cvta.to.shared.u64 t, %1; cvt.u32.u64 %0, t; }" : "=r"(a) : "l"(p));
    return a;
}

#if HAS_TC
__device__ __forceinline__ uint32_t elect_one() {
    uint32_t p;
    asm volatile("{\n\t.reg .pred p;\n\telect.sync _|p, 0xFFFFFFFF;\n\tselp.b32 %0, 1, 0, p;\n\t}" : "=r"(p));
    return p;
}
#define TC_ALLOC(sm, n)   asm volatile("tcgen05.alloc.cta_group::1.sync.aligned.shared::cta.b32 [%0], %1;" :: "r"(sm), "r"(n) : "memory")
#define TC_DEALLOC(t, n)  asm volatile("tcgen05.dealloc.cta_group::1.sync.aligned.b32 %0, %1;" :: "r"(t), "r"(n))
#define TC_RELINQ()       asm volatile("tcgen05.relinquish_alloc_permit.cta_group::1.sync.aligned;")
#define TC_COMMIT(mb)     asm volatile("tcgen05.commit.cta_group::1.mbarrier::arrive::one.shared::cluster.b64 [%0];" :: "r"(mb) : "memory")
#define TC_FENCE_AFTER()  asm volatile("tcgen05.fence::after_thread_sync;" ::: "memory")
#define TC_FENCE_BEFORE() asm volatile("tcgen05.fence::before_thread_sync;" ::: "memory")
#define TC_WAIT_LD()      asm volatile("tcgen05.wait::ld.sync.aligned;" ::: "memory")
#define FENCE_ASYNC()     asm volatile("fence.proxy.async.shared::cta;" ::: "memory")
#define MBAR_INIT(mb, c)  asm volatile("mbarrier.init.shared.b64 [%0], %1;" :: "r"(mb), "r"(c) : "memory")
#define MBAR_INVAL(mb)    asm volatile("mbarrier.inval.shared.b64 [%0];" :: "r"(mb) : "memory")
#define CP16(sa, gp)      asm volatile("cp.async.cg.shared.global [%0], [%1], 16;" :: "r"(sa), "l"(gp))
#define CP_COMMIT()       asm volatile("cp.async.commit_group;" ::: "memory")
#define CP_WAIT1()        asm volatile("cp.async.wait_group 1;" ::: "memory")
#define CP_WAIT0()        asm volatile("cp.async.wait_group 0;" ::: "memory")

#define MBAR_WAIT(mb, ph) do {                                              \
    uint32_t _m = (mb), _p = (ph), _d;                                      \
    asm volatile("{\n\t.reg .pred p;\n\t"                                   \
        "mbarrier.try_wait.parity.acquire.cta.shared::cta.b64 p, [%1], %2;\n\t" \
        "selp.b32 %0, 1, 0, p;\n\t}" : "=r"(_d) : "r"(_m), "r"(_p) : "memory"); \
    if (!_d) {                                                              \
        asm volatile("{\n\t.reg .pred P1;\n\t"                              \
            "WL_%=:\n\t"                                                    \
            "mbarrier.try_wait.parity.acquire.cta.shared::cta.b64 P1, [%0], %1, 0x989680;\n\t" \
            "@P1 bra.uni WD_%=;\n\t"                                        \
            "bra.uni WL_%=;\n\t"                                            \
            "WD_%=:\n\t}" :: "r"(_m), "r"(_p) : "memory");                  \
    }                                                                       \
} while (0)

__device__ __forceinline__ void mma_bf16_ss(uint32_t d, uint64_t da, uint64_t db,
                                            uint32_t idesc, uint32_t en) {
    asm volatile(
        "{\n\t.reg .pred p;\n\tsetp.ne.u32 p, %5, 0;\n\t"
        "tcgen05.mma.cta_group::1.kind::f16 [%0], %1, %2, %3, {%4,%4,%4,%4}, p;\n\t}"
        :: "r"(d), "l"(da), "l"(db), "r"(idesc), "r"(0u), "r"(en) : "memory");
}

__device__ __forceinline__ void ldtm_x32(uint32_t* r, uint32_t ta) {
    asm volatile(
        "tcgen05.ld.sync.aligned.32x32b.x32.b32 "
        "{%0,%1,%2,%3,%4,%5,%6,%7,%8,%9,%10,%11,%12,%13,%14,%15,"
        "%16,%17,%18,%19,%20,%21,%22,%23,%24,%25,%26,%27,%28,%29,%30,%31}, [%32];"
        : "=r"(r[0]),"=r"(r[1]),"=r"(r[2]),"=r"(r[3]),"=r"(r[4]),"=r"(r[5]),"=r"(r[6]),"=r"(r[7]),
          "=r"(r[8]),"=r"(r[9]),"=r"(r[10]),"=r"(r[11]),"=r"(r[12]),"=r"(r[13]),"=r"(r[14]),"=r"(r[15]),
          "=r"(r[16]),"=r"(r[17]),"=r"(r[18]),"=r"(r[19]),"=r"(r[20]),"=r"(r[21]),"=r"(r[22]),"=r"(r[23]),
          "=r"(r[24]),"=r"(r[25]),"=r"(r[26]),"=r"(r[27]),"=r"(r[28]),"=r"(r[29]),"=r"(r[30]),"=r"(r[31])
        : "r"(ta));
}

// SW64 descriptor base: layout=4, version=1, SBO=32, LBO=1 (64B rows, atom = 8r x 64B)
#define DESC_SW64 ((4ull<<61) | (1ull<<46) | (32ull<<32) | (1ull<<16))
#define MK_DESC64(a) (DESC_SW64 | ((uint64_t)((a) >> 4) & 0x3FFFull))
// idesc: f32 accum, A=BF16, B=BF16, M=128, N=256
#define GEMM_IDESC 0x08400490u
#endif  // HAS_TC

// ---------------- small utility kernels ----------------
__global__ void k_zero_f(float* p, int n) {
    int i = blockIdx.x * blockDim.x + threadIdx.x;
    if (i < n) p[i] = 0.f;
}

__global__ void k_zero_counts() {
    int i = blockIdx.x * blockDim.x + threadIdx.x;
    if (i < Nc) { g_deg[i] = 0; g_cnt[i] = 0; }
}

__global__ void k_starts(const int* __restrict__ edge_len) {
    int s = 0;
    for (int b = 0; b < Bc; b++) { g_starts[b] = s; s += edge_len[b]; }
    g_starts[Bc] = s;
}

// flatten + degree histogram in one pass
__global__ void k_flatten(const int* __restrict__ edge_index,
                          const int* __restrict__ relpos_idx,
                          const int* __restrict__ deprel_idx,
                          const int* __restrict__ deparc_idx,
                          const int* __restrict__ edge_len) {
    int i = blockIdx.x * blockDim.x + threadIdx.x;
    if (i >= BEc) return;
    int b = i >> 13;
    int e = i & (Ec - 1);
    if (e < edge_len[b]) {
        int p = g_starts[b] + e;
        int tg = edge_index[(size_t)i * 2 + 1] + b * Sc;
        g_src[p] = edge_index[(size_t)i * 2 + 0] + b * Sc;
        g_tgt[p] = tg;
        g_dr[p]  = deprel_idx[i];
        g_da[p]  = deparc_idx[i];
        g_rp[p]  = relpos_idx[i];
        atomicAdd(&g_deg[tg], 1);
    }
}

__global__ void k_scan() {
    __shared__ int sh[1024];
    int t = threadIdx.x;
    int base = t * 16;
    int loc[16];
    int tot = 0;
    #pragma unroll
    for (int j = 0; j < 16; j++) { loc[j] = tot; tot += g_deg[base + j]; }
    sh[t] = tot;
    __syncthreads();
    for (int off = 1; off < 1024; off <<= 1) {
        int v = (t >= off) ? sh[t - off] : 0;
        __syncthreads();
        sh[t] += v;
        __syncthreads();
    }
    int excl = sh[t] - tot;
    #pragma unroll
    for (int j = 0; j < 16; j++) g_rowptr[base + j] = excl + loc[j];
    if (t == 1023) g_rowptr[Nc] = sh[1023];
}

__global__ void k_scatter() {
    int i = blockIdx.x * blockDim.x + threadIdx.x;
    if (i >= g_starts[Bc]) return;
    int tg = g_tgt[i];
    int slot = g_rowptr[tg] + atomicAdd(&g_cnt[tg], 1);
    g_csr[slot] = i;
}

// ---------------- weight prep: transpose + bf16 split (tc path only) ----------------
__global__ void k_wprep(const float* __restrict__ Wq, const float* __restrict__ Wk,
                        const float* __restrict__ Wv, const float* __restrict__ Wo) {
#if HAS_TC
    int mat = blockIdx.y;
    int l = mat >> 2, m = mat & 3;
    const float* W = (m == 0 ? Wq : m == 1 ? Wk : m == 2 ? Wv : Wo) + (size_t)l * Dc * Dc;
    int i = blockIdx.x * 256 + threadIdx.x;
    int n = i & 511, k = i >> 9;
    float v = W[(size_t)k * 512 + n];
    __nv_bfloat16 hi = __float2bfloat16(v);
    float lo = v - __bfloat162float(hi);
    size_t o = (size_t)mat * 262144 + (size_t)n * 512 + k;
    g_wh[o] = hi;
    g_wl[o] = __float2bfloat16(lo);
#endif
}

// ---------------- activation split (input only) ----------------
__global__ void k_split(const float* __restrict__ ext) {
#if HAS_TC
    int i = blockIdx.x * 256 + threadIdx.x;
    float v = ext[i];
    __nv_bfloat16 hi = __float2bfloat16(v);
    g_ah[i] = hi;
    g_al[i] = __float2bfloat16(v - __bfloat162float(hi));
#endif
}

// ---------------- tcgen05 GEMM (sm_103a only) ----------------
// mode 0: fused QKV grid (6,128): x -> {q,k,v} x {N-half}; mode 1: O-proj grid (2,128).
// 128M x 256N per CTA, K=32 chunks (SW64), double-buffered 48KB, cp.async prefetch,
// N=256 MMA dispatches. ~99KB SMEM -> 2 CTAs/SM.
#define BUF_BYTES 49152
__global__ __launch_bounds__(256) void gemm_tc(int l, int mode) {
#if HAS_TC
    __shared__ uint32_t s_tmem[1];
    __shared__ __align__(8) unsigned long long s_mbar[2];
    extern __shared__ __align__(16) char dsm[];

    const int tid = threadIdx.x;
    const int wid = tid >> 5, lane = tid & 31;

    int mi, half;
    if (mode == 0) { mi = blockIdx.x >> 1; half = blockIdx.x & 1; }
    else           { mi = 3;               half = blockIdx.x; }
    const int mat = l * 4 + mi;
    float* C = (mi == 0) ? g_q : (mi == 1 ? g_k : (mi == 2 ? g_v : g_tmp));
    const int bm0 = blockIdx.y * 128;
    const int bn0 = half * 256;

    uint32_t dyn0 = smem_u32(dsm);
    uint32_t base = (dyn0 + 1023) & ~1023u;
    char* pb = dsm + (base - dyn0);
    const uint32_t mb[2] = { smem_u32(&s_mbar[0]), smem_u32(&s_mbar[1]) };

    const __nv_bfloat16* __restrict__ Wh = g_wh + (size_t)mat * 262144;
    const __nv_bfloat16* __restrict__ Wl = g_wl + (size_t)mat * 262144;

    if (wid == 0) {
        TC_ALLOC(smem_u32(s_tmem), 256);
        TC_RELINQ();
    }
    if (tid == 0) { MBAR_INIT(mb[0], 1); MBAR_INIT(mb[1], 1); }
    __syncthreads();
    uint32_t tmem;
    asm volatile("ld.shared.b32 %0, [%1];" : "=r"(tmem) : "r"(smem_u32(s_tmem)));

    auto load_chunk = [&](int j) {
        const uint32_t bufo = base + (uint32_t)(j & 1) * BUF_BYTES;
        const int k0 = j * 32;
        #pragma unroll
        for (int it = 0; it < 2; it++) {
            int u = tid + it * 256;
            int row = u >> 2, c16 = u & 3;
            uint32_t off = (uint32_t)row * 64 + (uint32_t)c16 * 16;
            uint32_t sw = off ^ ((off >> 3) & 0x30);
            const char* gh = (const char*)(g_ah + (size_t)(bm0 + row) * 512 + k0) + c16 * 16;
            const char* gl = (const char*)(g_al + (size_t)(bm0 + row) * 512 + k0) + c16 * 16;
            CP16(bufo + sw, gh);
            CP16(bufo + 8192 + sw, gl);
        }
        #pragma unroll
        for (int it = 0; it < 4; it++) {
            int u = tid + it * 256;
            int row = u >> 2, c16 = u & 3;
            uint32_t off = (uint32_t)row * 64 + (uint32_t)c16 * 16;
            uint32_t sw = off ^ ((off >> 3) & 0x30);
            const char* gh = (const char*)(Wh + (size_t)(bn0 + row) * 512 + k0) + c16 * 16;
            const char* gl = (const char*)(Wl + (size_t)(bn0 + row) * 512 + k0) + c16 * 16;
            CP16(bufo + 16384 + sw, gh);
            CP16(bufo + 32768 + sw, gl);
        }
        CP_COMMIT();
    };

    load_chunk(0);
    for (int c = 0; c < 16; c++) {
        const int j = c + 1;
        if (j < 16) {
            if (j >= 2) MBAR_WAIT(mb[j & 1], ((j - 2) >> 1) & 1);
            load_chunk(j);
            CP_WAIT1();
        } else {
            CP_WAIT0();
        }
        __syncthreads();

        if (wid == 0) {
            if (elect_one()) {
                FENCE_ASYNC();
                const uint32_t bufo = base + (uint32_t)(c & 1) * BUF_BYTES;
                const uint64_t dAh = MK_DESC64(bufo);
                const uint64_t dAl = MK_DESC64(bufo + 8192);
                const uint64_t dBh = MK_DESC64(bufo + 16384);
                const uint64_t dBl = MK_DESC64(bufo + 32768);
                #pragma unroll
                for (int ks = 0; ks < 2; ks++) {
                    const uint64_t ofs = (uint64_t)(ks * 2);
                    mma_bf16_ss(tmem, dAh + ofs, dBh + ofs, GEMM_IDESC,
                                (c == 0 && ks == 0) ? 0u : 1u);
                    mma_bf16_ss(tmem, dAh + ofs, dBl + ofs, GEMM_IDESC, 1u);
                    mma_bf16_ss(tmem, dAl + ofs, dBh + ofs, GEMM_IDESC, 1u);
                }
                TC_COMMIT(mb[c & 1]);
            }
        }
    }
    MBAR_WAIT(mb[0], 1);
    MBAR_WAIT(mb[1], 1);
    TC_FENCE_AFTER();

    // epilogue: two 128-col passes; TMEM -> padded SMEM stage (stride 129) -> global
    float* stage = (float*)pb;
    const int rrow = (wid & 3) * 32 + lane;
    const int q0 = (wid >> 2) * 64;
    #pragma unroll
    for (int p = 0; p < 2; p++) {
        #pragma unroll
        for (int cb = 0; cb < 2; cb++) {
            uint32_t regs[32];
            ldtm_x32(regs, tmem + p * 128 + q0 + cb * 32);
            TC_WAIT_LD();
            #pragma unroll
            for (int j = 0; j < 32; j++)
                stage[rrow * 129 + q0 + cb * 32 + j] = __uint_as_float(regs[j]);
        }
        TC_FENCE_BEFORE();
        __syncthreads();
        {
            int col = tid & 127;
            int rb = tid >> 7;
            for (int r = rb; r < 128; r += 2)
                C[(size_t)(bm0 + r) * 512 + bn0 + p * 128 + col] = stage[r * 129 + col];
        }
        __syncthreads();
    }
    if (tid == 0) { MBAR_INVAL(mb[0]); MBAR_INVAL(mb[1]); }
    if (wid == 0) TC_DEALLOC(tmem, 256);
#endif  // HAS_TC
}

// ---------------- SIMT fallback SGEMM (empty when tcgen05 path is compiled) -------
#define GM 16384
#define GN 512
#define GK 512
__global__ __launch_bounds__(256) void gemm_simt(const float* __restrict__ Aext,
                                                 const float* __restrict__ Bw,
                                                 int asel, int csel) {
#if !HAS_TC
    const float* A = (asel == 0) ? Aext : (asel == 1 ? g_h : g_agg);
    float* C = (csel == 0) ? g_q : (csel == 1 ? g_k : (csel == 2 ? g_v : g_tmp));

    __shared__ float As[8][128];
    __shared__ float Bs[8][128];

    int bm0 = blockIdx.y * 128;
    int bn0 = blockIdx.x * 128;
    int t = threadIdx.x;
    int ty = t >> 4, tx = t & 15;

    int arow = t >> 1;
    int acol = (t & 1) * 4;
    int brow = t >> 5;
    int bcol = (t & 31) * 4;

    float acc[8][8];
    #pragma unroll
    for (int i = 0; i < 8; i++)
        #pragma unroll
        for (int j = 0; j < 8; j++) acc[i][j] = 0.f;

    for (int k0 = 0; k0 < GK; k0 += 8) {
        float4 av = *(const float4*)(A + (size_t)(bm0 + arow) * GK + k0 + acol);
        As[acol + 0][arow] = av.x;
        As[acol + 1][arow] = av.y;
        As[acol + 2][arow] = av.z;
        As[acol + 3][arow] = av.w;
        float4 bv = *(const float4*)(Bw + (size_t)(k0 + brow) * GN + bn0 + bcol);
        *(float4*)&Bs[brow][bcol] = bv;
        __syncthreads();
        #pragma unroll
        for (int kk = 0; kk < 8; kk++) {
            float4 a0 = *(float4*)&As[kk][ty * 8];
            float4 a1 = *(float4*)&As[kk][ty * 8 + 4];
            float4 b0 = *(float4*)&Bs[kk][tx * 8];
            float4 b1 = *(float4*)&Bs[kk][tx * 8 + 4];
            float a[8] = {a0.x, a0.y, a0.z, a0.w, a1.x, a1.y, a1.z, a1.w};
            float b[8] = {b0.x, b0.y, b0.z, b0.w, b1.x, b1.y, b1.z, b1.w};
            #pragma unroll
            for (int i = 0; i < 8; i++)
                #pragma unroll
                for (int j = 0; j < 8; j++)
                    acc[i][j] += a[i] * b[j];
        }
        __syncthreads();
    }
    #pragma unroll
    for (int i = 0; i < 8; i++) {
        float* crow = C + (size_t)(bm0 + ty * 8 + i) * GN + bn0 + tx * 8;
        float4 c0 = {acc[i][0], acc[i][1], acc[i][2], acc[i][3]};
        float4 c1 = {acc[i][4], acc[i][5], acc[i][6], acc[i][7]};
        *(float4*)(crow) = c0;
        *(float4*)(crow + 4) = c1;
    }
#endif  // !HAS_TC
}

// ---------------- per-edge logits (flat order, rel inline, writes g_rel) ----------
__global__ void k_logit(const float* __restrict__ dre,
                        const float* __restrict__ dae,
                        const float* __restrict__ rpe) {
    int w = (blockIdx.x * blockDim.x + threadIdx.x) >> 5;   // edge
    int lane = threadIdx.x & 31;
    if (w >= g_starts[Bc]) return;
    int src = g_src[w], tgt = g_tgt[w];
    int l16 = lane & 15, grp = lane >> 4;

    float4 r4;
    {
        float4 a = ((const float4*)(dre + (size_t)g_dr[w] * DKc))[l16];
        float4 b = ((const float4*)(dae + (size_t)g_da[w] * DKc))[l16];
        float4 c = ((const float4*)(rpe + (size_t)g_rp[w] * DKc))[l16];
        r4 = make_float4(a.x + b.x + c.x, a.y + b.y + c.y,
                         a.z + b.z + c.z, a.w + b.w + c.w);
        if (grp == 0) ((float4*)(g_rel + (size_t)w * DKc))[l16] = r4;
    }

    const float4* qb = (const float4*)(g_q + (size_t)tgt * HDc);
    const float4* kb = (const float4*)(g_k + (size_t)src * HDc);
    #pragma unroll
    for (int h2 = 0; h2 < 4; h2++) {
        int h = h2 * 2 + grp;
        float4 q4 = qb[h * 16 + l16];
        float4 k4 = kb[h * 16 + l16];
        float acc = q4.x * (k4.x + r4.x) + q4.y * (k4.y + r4.y)
                  + q4.z * (k4.z + r4.z) + q4.w * (k4.w + r4.w);
        acc += __shfl_xor_sync(0xffffffffu, acc, 8);
        acc += __shfl_xor_sync(0xffffffffu, acc, 4);
        acc += __shfl_xor_sync(0xffffffffu, acc, 2);
        acc += __shfl_xor_sync(0xffffffffu, acc, 1);
        if (l16 == 0) g_logit[w * Hc + h] = acc * 0.125f;
    }
}

// ---------------- fused softmax-stats + aggregate (block per node) ----------------
__global__ __launch_bounds__(128) void k_aggs(float* __restrict__ attn_out) {
    const int n = blockIdx.x;
    const int t = threadIdx.x;
    const int beg = g_rowptr[n], end = g_rowptr[n + 1];

    __shared__ float sfm[8], sfd[8];

    if (t < 64) {
        const int h = t >> 3, wkr = t & 7;
        float m = -1e30f, d = 0.f;
        for (int e = beg + wkr; e < end; e += 8) {
            float lg = g_logit[(size_t)g_csr[e] * Hc + h];
            float nm = fmaxf(m, lg);
            d = d * __expf(m - nm) + __expf(lg - nm);
            m = nm;
        }
        #pragma unroll
        for (int off = 4; off; off >>= 1) {
            float om = __shfl_xor_sync(0xffffffffu, m, off);
            float od = __shfl_xor_sync(0xffffffffu, d, off);
            float nm = fmaxf(m, om);
            d = d * __expf(m - nm) + od * __expf(om - nm);
            m = nm;
        }
        if (wkr == 0) { sfm[h] = m; sfd[h] = d + 1e-9f; }
    }
    __syncthreads();

    const int dim0 = t * 4;
    const int h = dim0 >> 6;
    const int d0 = dim0 & 63;
    const float mh = sfm[h];
    const float dh = sfd[h];
    float acc0 = 0.f, acc1 = 0.f, acc2 = 0.f, acc3 = 0.f;
    for (int e = beg; e < end; e++) {
        int i = g_csr[e];
        float alpha = __expf(g_logit[(size_t)i * Hc + h] - mh) / dh;
        int src = g_src[i];
        const float* vp = g_v + (size_t)src * HDc + dim0;
        const float* rp = g_rel + (size_t)i * DKc + d0;
        acc0 += alpha * (vp[0] + rp[0]);
        acc1 += alpha * (vp[1] + rp[1]);
        acc2 += alpha * (vp[2] + rp[2]);
        acc3 += alpha * (vp[3] + rp[3]);
        if ((t & 15) == 0) attn_out[(size_t)i * Hc + h] = alpha;
    }
    size_t o = (size_t)n * HDc + dim0;
    float* ap = g_agg + o;
    ap[0] = acc0; ap[1] = acc1; ap[2] = acc2; ap[3] = acc3;
#if HAS_TC
    float vv[4] = {acc0, acc1, acc2, acc3};
    #pragma unroll
    for (int j = 0; j < 4; j++) {
        __nv_bfloat16 hi = __float2bfloat16(vv[j]);
        g_ah[o + j] = hi;
        g_al[o + j] = __float2bfloat16(vv[j] - __bfloat162float(hi));
    }
#endif
}

// ---------------- residual + LayerNorm (+ReLU); emits next-layer bf16 split -------
__global__ void k_ln(const float* __restrict__ hin_ext, int use_ext,
                     const float* __restrict__ lnsc,
                     const float* __restrict__ lnbi,
                     float* __restrict__ reps_out, int do_relu) {
    int n = blockIdx.x;
    int t = threadIdx.x;
    int lane = t & 31, warp = t >> 5;
    const float* hin = use_ext ? hin_ext : g_h;
    const float* row = g_tmp + (size_t)n * Dc;
    const float* hrow = hin + (size_t)n * Dc;
    float x[4];
    float s = 0.f;
    #pragma unroll
    for (int j = 0; j < 4; j++) {
        x[j] = row[t * 4 + j] + hrow[t * 4 + j];
        s += x[j];
    }
    __shared__ float red[4];
    #pragma unroll
    for (int off = 16; off; off >>= 1) s += __shfl_xor_sync(0xffffffffu, s, off);
    if (lane == 0) red[warp] = s;
    __syncthreads();
    float mean = (red[0] + red[1] + red[2] + red[3]) * (1.f / Dc);
    __syncthreads();
    float vs = 0.f;
    #pragma unroll
    for (int j = 0; j < 4; j++) { float d = x[j] - mean; vs += d * d; }
    #pragma unroll
    for (int off = 16; off; off >>= 1) vs += __shfl_xor_sync(0xffffffffu, vs, off);
    if (lane == 0) red[warp] = vs;
    __syncthreads();
    float var = (red[0] + red[1] + red[2] + red[3]) * (1.f / Dc);
    float inv = rsqrtf(var + 1e-5f);
    #pragma unroll
    for (int j = 0; j < 4; j++) {
        int dim = t * 4 + j;
        float y = (x[j] - mean) * inv * lnsc[dim] + lnbi[dim];
        if (do_relu) y = fmaxf(y, 0.f);
        size_t o = (size_t)n * Dc + dim;
        reps_out[o] = y;
        g_h[o] = y;
#if HAS_TC
        __nv_bfloat16 hi = __float2bfloat16(y);
        g_ah[o] = hi;
        g_al[o] = __float2bfloat16(y - __bfloat162float(hi));
#endif
    }
}

// ---------------- launch ----------------
extern "C" void kernel_launch(void* const* d_in, const int* in_sizes, int n_in,
                              void* d_out, int out_size) {
    const float* inp        = (const float*)d_in[0];
    const int*   edge_len   = (const int*)d_in[2];
    const int*   edge_index = (const int*)d_in[3];
    const int*   relpos_idx = (const int*)d_in[4];
    const int*   deprel_idx = (const int*)d_in[6];
    const int*   deparc_idx = (const int*)d_in[7];
    const float* Wq  = (const float*)d_in[14];
    const float* Wk  = (const float*)d_in[15];
    const float* Wv  = (const float*)d_in[16];
    const float* Wo  = (const float*)d_in[17];
    const float* dre = (const float*)d_in[18];
    const float* dae = (const float*)d_in[19];
    const float* rpe = (const float*)d_in[20];
    const float* lnsc = (const float*)d_in[21];
    const float* lnbi = (const float*)d_in[22];

    float* out  = (float*)d_out;
    float* reps = out;                          // (L, N, D)
    float* attn = out + (size_t)Lc * Nc * Dc;   // (L, BE, H)

    const int GEMM_SMEM = 2 * BUF_BYTES + 1024;   // 99328 -> 2 CTAs/SM
    cudaFuncSetAttribute(gemm_tc, cudaFuncAttributeMaxDynamicSharedMemorySize, GEMM_SMEM);

    // which GEMM path did this cubin compile? (tc body ~64 regs; empty ~<10)
    cudaFuncAttributes fa_tc{};
    cudaFuncGetAttributes(&fa_tc, gemm_tc);
    const bool use_tc = fa_tc.numRegs > 32;

    dim3 ggrid_qkv(6, 128);
    dim3 ggrid_o(2, 128);
    dim3 ggrid_simt(4, 128);

    // prep needed by first GEMM (keeps first gemm_tc at my 4th launch for ncu)
    k_wprep<<<dim3(1024, 8), 256>>>(Wq, Wk, Wv, Wo);
    k_split<<<(Nc * Dc) / 256, 256>>>(inp);
    k_zero_f<<<(Lc * BEc * Hc + 255) / 256, 256>>>(attn, Lc * BEc * Hc);

    // layer-0 QKV (fused)
    if (use_tc) {
        gemm_tc<<<ggrid_qkv, 256, GEMM_SMEM>>>(0, 0);
    } else {
        gemm_simt<<<ggrid_simt, 256>>>(inp, Wq, 0, 0);
        gemm_simt<<<ggrid_simt, 256>>>(inp, Wk, 0, 1);
        gemm_simt<<<ggrid_simt, 256>>>(inp, Wv, 0, 2);
    }

    // edge preprocessing (independent of GEMMs)
    k_zero_counts<<<(Nc + 255) / 256, 256>>>();
    k_starts<<<1, 1>>>(edge_len);
    k_flatten<<<BEc / 256, 256>>>(edge_index, relpos_idx, deprel_idx, deparc_idx, edge_len);
    k_scan<<<1, 1024>>>();
    k_scatter<<<BEc / 256, 256>>>();

    for (int l = 0; l < Lc; l++) {
        if (l > 0) {
            const size_t woff = (size_t)l * Dc * HDc;
            if (use_tc) {
                gemm_tc<<<ggrid_qkv, 256, GEMM_SMEM>>>(l, 0);
            } else {
                gemm_simt<<<ggrid_simt, 256>>>(inp, Wq + woff, 1, 0);
                gemm_simt<<<ggrid_simt, 256>>>(inp, Wk + woff, 1, 1);
                gemm_simt<<<ggrid_simt, 256>>>(inp, Wv + woff, 1, 2);
            }
        }

        k_logit<<<(BEc * 32) / 256, 256>>>(dre + (size_t)l * 50 * DKc,
                                           dae + (size_t)l * 3 * DKc,
                                           rpe + (size_t)l * 21 * DKc);
        k_aggs<<<Nc, 128>>>(attn + (size_t)l * BEc * Hc);

        if (use_tc) {
            gemm_tc<<<ggrid_o, 256, GEMM_SMEM>>>(l, 1);    // agg @ Wo -> g_tmp
        } else {
            gemm_simt<<<ggrid_simt, 256>>>(inp, Wo + (size_t)l * HDc * Dc, 2, 3);
        }

        k_ln<<<Nc, 128>>>(inp, (l == 0) ? 1 : 0,
                          lnsc + (size_t)l * Dc, lnbi + (size_t)l * Dc,
                          reps + (size_t)l * Nc * Dc, (l < Lc - 1) ? 1 : 0);
    }
}